// round 1
// baseline (speedup 1.0000x reference)
#include <cuda_runtime.h>

// Problem constants (from reference):
//   input  (2,3,345,456) fp32
//   pass 1: width  456 -> 272, scale = 456/272, invscale = 272/456
//   pass 2: height 345 -> 271, scale = 345/271, invscale = 271/345
//   output (2,3,271,272) fp32
#define H_IN  345
#define W_IN  456
#define H_OUT 271
#define W_OUT 272
#define NCH   6       // 2*3 batch*channel planes
#define KS    5       // max taps

// Compute the KS triangle-filter taps for output coordinate `o`, matching the
// aten decomposition exactly: truncating int cast, clamp bounds, tap masking
// by window size, per-pixel weight normalization, clamped gather indices.
__device__ __forceinline__ void compute_taps(int o, float scale, float invscale,
                                             int in_size, int* idx, float* w) {
    float center = ((float)o + 0.5f) * scale;
    int xmin = max((int)(center - scale + 0.5f), 0);   // (int) truncates toward 0, same as astype(int64)
    int xmax = min((int)(center + scale + 0.5f), in_size);
    int size = min(xmax - xmin, KS);
    float sum = 0.0f;
#pragma unroll
    for (int j = 0; j < KS; j++) {
        float ww = 1.0f - fminf(fabsf(((float)(j + xmin) - center + 0.5f) * invscale), 1.0f);
        ww = (j < size) ? ww : 0.0f;
        w[j] = ww;
        sum += ww;
        idx[j] = min(j + xmin, in_size - 1);
    }
#pragma unroll
    for (int j = 0; j < KS; j++) w[j] = w[j] / sum;
}

__global__ __launch_bounds__(256) void Repro_79422535238141_kernel(
    const float* __restrict__ in, float* __restrict__ out) {
    const float SCALE_W = (float)(456.0 / 272.0);
    const float INV_W   = (float)(272.0 / 456.0);
    const float SCALE_H = (float)(345.0 / 271.0);
    const float INV_H   = (float)(271.0 / 345.0);

    int x = blockIdx.x * 32 + threadIdx.x;
    int y = blockIdx.y * 8 + threadIdx.y;
    int c = blockIdx.z;
    if (x >= W_OUT || y >= H_OUT) return;

    int   hidx[KS]; float hw[KS];
    compute_taps(x, SCALE_W, INV_W, W_IN, hidx, hw);
    int   vidx[KS]; float vw[KS];
    compute_taps(y, SCALE_H, INV_H, H_IN, vidx, vw);

    const float* plane = in + (size_t)c * (H_IN * W_IN);

    float acc = 0.0f;
#pragma unroll
    for (int ky = 0; ky < KS; ky++) {
        const float* row = plane + vidx[ky] * W_IN;
        float h = 0.0f;
#pragma unroll
        for (int kx = 0; kx < KS; kx++) {
            h = fmaf(__ldg(row + hidx[kx]), hw[kx], h);
        }
        acc = fmaf(h, vw[ky], acc);
    }
    out[(size_t)c * (H_OUT * W_OUT) + y * W_OUT + x] = acc;
}

extern "C" void kernel_launch(void* const* d_in, const int* in_sizes, int n_in,
                              void* d_out, int out_size) {
    const float* in = (const float*)d_in[0];
    float* out = (float*)d_out;
    dim3 block(32, 8, 1);
    dim3 grid((W_OUT + 31) / 32, (H_OUT + 7) / 8, NCH);
    Repro_79422535238141_kernel<<<grid, block>>>(in, out);
}

// round 6
// speedup vs baseline: 1.3219x; 1.3219x over previous
#include <cuda_runtime.h>

// input  (2,3,345,456) fp32  -> H-pass -> mid (2,3,345,272) -> V-pass -> (2,3,271,272)
#define H_IN  345
#define W_IN  456
#define H_OUT 271
#define W_OUT 272
#define W_OUT4 68          // W_OUT / 4
#define NCH   6
#define KS    5
#define ROWS_TOTAL (NCH * H_IN)   // 2070 — input is [2070][456] linear, mid is [2070][272]

__device__ __align__(16) float g_mid[ROWS_TOTAL * W_OUT];

// Triangle-filter taps matching the aten decomposition: truncating int cast,
// clamp bounds, tap masking by window size, per-pixel weight normalization.
__device__ __forceinline__ void taps(int o, float scale, float invscale, int in_size,
                                     int idx[KS], float w[KS]) {
    float center = ((float)o + 0.5f) * scale;
    int xmin = max((int)(center - scale + 0.5f), 0);      // trunc toward zero == astype(int64)
    int xmax = min((int)(center + scale + 0.5f), in_size);
    int size = min(xmax - xmin, KS);
    float sum = 0.0f;
#pragma unroll
    for (int j = 0; j < KS; j++) {
        float ww = 1.0f - fminf(fabsf(((float)(j + xmin) - center + 0.5f) * invscale), 1.0f);
        ww = (j < size) ? ww : 0.0f;
        w[j] = ww;
        sum += ww;
        idx[j] = min(j + xmin, in_size - 1);
    }
    float rs = 1.0f / sum;
#pragma unroll
    for (int j = 0; j < KS; j++) w[j] *= rs;
}

// ---------------- Horizontal pass: 456 -> 272 along last dim ----------------
// Thread owns output column x (taps computed once), streams 5 rows.
// blockDim (32,8); grid (ceil(272/32)=9, ceil(2070/40)=52).
__global__ __launch_bounds__(256) void hpass_kernel(const float* __restrict__ in) {
    int x = blockIdx.x * 32 + threadIdx.x;
    if (x >= W_OUT) return;

    int idx[KS]; float w[KS];
    taps(x, (float)(456.0 / 272.0), (float)(272.0 / 456.0), W_IN, idx, w);

    int r0 = blockIdx.y * 40 + threadIdx.y;   // rows r0, r0+8, ..., r0+32
#pragma unroll
    for (int i = 0; i < 5; i++) {
        int r = r0 + i * 8;
        if (r < ROWS_TOTAL) {
            const float* row = in + r * W_IN;
            float a = 0.0f;
#pragma unroll
            for (int j = 0; j < KS; j++)
                a = fmaf(__ldg(row + idx[j]), w[j], a);
            g_mid[r * W_OUT + x] = a;
        }
    }
}

// ---------------- Vertical pass: 345 -> 271 along row dim ----------------
// Thread owns output row y (taps computed once), streams x in float4 chunks.
// blockDim (32,8); grid (1, ceil(271/8)=34, 6). Thread covers float4 cols
// tx, tx+32, tx+64 (68 total -> 3 ragged iterations).
__global__ __launch_bounds__(256) void vpass_kernel(float* __restrict__ out) {
    int y = blockIdx.y * 8 + threadIdx.y;
    if (y >= H_OUT) return;
    int c = blockIdx.z;

    int idx[KS]; float w[KS];
    taps(y, (float)(345.0 / 271.0), (float)(271.0 / 345.0), H_IN, idx, w);

    const float4* mid4 = reinterpret_cast<const float4*>(g_mid) + c * (H_IN * W_OUT4);
    float4* orow4 = reinterpret_cast<float4*>(out) + (c * H_OUT + y) * W_OUT4;

#pragma unroll
    for (int i = 0; i < 3; i++) {
        int col = threadIdx.x + i * 32;
        if (col < W_OUT4) {
            float4 a = make_float4(0.f, 0.f, 0.f, 0.f);
#pragma unroll
            for (int j = 0; j < KS; j++) {
                float4 v = mid4[idx[j] * W_OUT4 + col];
                float wj = w[j];
                a.x = fmaf(v.x, wj, a.x);
                a.y = fmaf(v.y, wj, a.y);
                a.z = fmaf(v.z, wj, a.z);
                a.w = fmaf(v.w, wj, a.w);
            }
            orow4[col] = a;
        }
    }
}

extern "C" void kernel_launch(void* const* d_in, const int* in_sizes, int n_in,
                              void* d_out, int out_size) {
    const float* in = (const float*)d_in[0];
    float* out = (float*)d_out;

    dim3 hblock(32, 8, 1);
    dim3 hgrid((W_OUT + 31) / 32, (ROWS_TOTAL + 39) / 40, 1);
    hpass_kernel<<<hgrid, hblock>>>(in);

    dim3 vblock(32, 8, 1);
    dim3 vgrid(1, (H_OUT + 7) / 8, NCH);
    vpass_kernel<<<vgrid, vblock>>>(out);
}